// round 9
// baseline (speedup 1.0000x reference)
#include <cuda_runtime.h>

#define T_STEPS 2000
#define N_IN    8192
#define N_OUT   4096

// 32 MB scratch for lif_input = x @ W^T  (allocation-free: __device__ global)
__device__ float g_lif[(size_t)T_STEPS * N_OUT];

// ---------------------------------------------------------------------------
// Phase 1: fp32 GEMM, 128x64 tiles for SM load balance (1024 tiles, occ 3).
// Per-output math: ascending-k fp32 fma chain — identical to the passing R1.
// ---------------------------------------------------------------------------
constexpr int BM = 128, BN = 64, BK = 8, TM = 8, TN = 4;

__global__ __launch_bounds__(256, 3)
void gemm_nt_kernel(const float* __restrict__ A,   // [M,K]
                    const float* __restrict__ B,   // [N,K]
                    float* __restrict__ C,         // [M,N]
                    int M, int N, int K)
{
    __shared__ float As[BK][BM];   // 4 KB
    __shared__ float Bs[BK][BN];   // 2 KB

    const int tid = threadIdx.x;
    const int bm  = blockIdx.y * BM;
    const int bn  = blockIdx.x * BN;

    // A loader: 128 rows x 8k -> 256 float4, one per thread
    const int aRow = tid >> 1;
    const int aCol = (tid & 1) * 4;
    // B loader: 64 rows x 8k -> 128 float4, threads 0..127
    const int bRow = tid >> 1;          // valid for tid < 128
    const int bCol = (tid & 1) * 4;

    // compute: 16(m) x 16(n) threads, micro-tile 8m x 4n
    const int tr = (tid >> 4) * TM;     // 0..120
    const int tc = (tid & 15) * TN;     // 0..60

    float acc[TM][TN];
    #pragma unroll
    for (int i = 0; i < TM; i++)
        #pragma unroll
        for (int j = 0; j < TN; j++)
            acc[i][j] = 0.0f;

    const bool aValid = (bm + aRow) < M;
    const float* Aptr = A + (size_t)(bm + aRow) * K + aCol;
    const float* Bptr = B + (size_t)(bn + bRow) * K + bCol;

    for (int k0 = 0; k0 < K; k0 += BK) {
        float4 a4 = aValid ? *(const float4*)(Aptr + k0)
                           : make_float4(0.f, 0.f, 0.f, 0.f);
        As[aCol + 0][aRow] = a4.x;
        As[aCol + 1][aRow] = a4.y;
        As[aCol + 2][aRow] = a4.z;
        As[aCol + 3][aRow] = a4.w;

        if (tid < 128) {
            float4 b4 = *(const float4*)(Bptr + k0);
            Bs[bCol + 0][bRow] = b4.x;
            Bs[bCol + 1][bRow] = b4.y;
            Bs[bCol + 2][bRow] = b4.z;
            Bs[bCol + 3][bRow] = b4.w;
        }
        __syncthreads();

        #pragma unroll
        for (int k = 0; k < BK; k++) {
            float ar[TM], br[TN];
            #pragma unroll
            for (int i = 0; i < TM; i++) ar[i] = As[k][tr + i];
            #pragma unroll
            for (int j = 0; j < TN; j++) br[j] = Bs[k][tc + j];
            #pragma unroll
            for (int i = 0; i < TM; i++)
                #pragma unroll
                for (int j = 0; j < TN; j++)
                    acc[i][j] += ar[i] * br[j];   // ascending-k fma chain
        }
        __syncthreads();
    }

    #pragma unroll
    for (int i = 0; i < TM; i++) {
        int gm = bm + tr + i;
        if (gm < M) {
            float4 v = make_float4(acc[i][0], acc[i][1], acc[i][2], acc[i][3]);
            *(float4*)(C + (size_t)gm * N + bn + tc) = v;
        }
    }
}

// ---------------------------------------------------------------------------
// Phase 2: LIF scan — unchanged from R8 (91 us, rel_err 0.0)
// ---------------------------------------------------------------------------
constexpr int PF = 16;          // 1999 = 16 (prime) + 123*16 + 15 (tail)
constexpr int NBATCH = 123;
constexpr int TAIL = 15;

__device__ __forceinline__ float lif_step(float inp, float& v, float& refrac,
                                          float dt_tau, float rest, float th,
                                          float rst, float trf)
{
    const float DT = 0.001f;
    float v1 = v - dt_tau * (v - rest);
    float va = v1 + inp;
    v1 = (refrac == 0.0f) ? va : v1;
    float rf = refrac - DT;
    rf = (refrac > 0.0f) ? rf : 0.0f;
    float spike = (v1 - th >= 0.0f) ? 1.0f : 0.0f;
    bool sb = (spike > 0.0f);
    refrac = sb ? trf : rf;
    v = sb ? rst : v1;
    return spike;
}

__global__ __launch_bounds__(32)
void lif_scan_kernel(const float* __restrict__ lif,
                     float* __restrict__ out,
                     const float* __restrict__ v_th,
                     const float* __restrict__ v_rest,
                     const float* __restrict__ v_reset,
                     const float* __restrict__ t_ref,
                     const float* __restrict__ tau)
{
    const int n = blockIdx.x * 32 + threadIdx.x;

    const float th   = v_th[n];
    const float rest = v_rest[n];
    const float rst  = v_reset[n];
    const float trf  = t_ref[n];
    const float dt_tau = 0.001f * tau[n];

    float v = rest;
    float refrac = 0.0f;
    out[n] = 0.0f;

    const float* p = lif + (size_t)1 * N_OUT + n;
    float*       q = out + (size_t)1 * N_OUT + n;

    float buf[PF];
    #pragma unroll
    for (int j = 0; j < PF; j++) buf[j] = p[(size_t)j * N_OUT];
    p += (size_t)PF * N_OUT;

    for (int b = 0; b < NBATCH; b++) {
        float cur[PF];
        #pragma unroll
        for (int j = 0; j < PF; j++) cur[j] = buf[j];
        #pragma unroll
        for (int j = 0; j < PF; j++) buf[j] = p[(size_t)j * N_OUT];
        p += (size_t)PF * N_OUT;
        #pragma unroll
        for (int j = 0; j < PF; j++)
            q[(size_t)j * N_OUT] =
                lif_step(cur[j], v, refrac, dt_tau, rest, th, rst, trf);
        q += (size_t)PF * N_OUT;
    }

    {
        float tail[TAIL];
        #pragma unroll
        for (int j = 0; j < TAIL; j++) tail[j] = p[(size_t)j * N_OUT];
        #pragma unroll
        for (int j = 0; j < PF; j++)
            q[(size_t)j * N_OUT] =
                lif_step(buf[j], v, refrac, dt_tau, rest, th, rst, trf);
        q += (size_t)PF * N_OUT;
        #pragma unroll
        for (int j = 0; j < TAIL; j++)
            q[(size_t)j * N_OUT] =
                lif_step(tail[j], v, refrac, dt_tau, rest, th, rst, trf);
    }
}

// ---------------------------------------------------------------------------
extern "C" void kernel_launch(void* const* d_in, const int* in_sizes, int n_in,
                              void* d_out, int out_size)
{
    const float* x       = (const float*)d_in[0];  // [T, N_IN]
    const float* weight  = (const float*)d_in[1];  // [N_OUT, N_IN]
    const float* v_th    = (const float*)d_in[2];
    const float* v_rest  = (const float*)d_in[3];
    const float* v_reset = (const float*)d_in[4];
    const float* t_ref   = (const float*)d_in[5];
    const float* tau     = (const float*)d_in[6];
    float* out = (float*)d_out;                    // [T, N_OUT]

    float* lif_ptr = nullptr;
    cudaGetSymbolAddress((void**)&lif_ptr, g_lif);

    // GEMM: 1024 tiles of 128x64 for per-SM balance
    dim3 grid(N_OUT / BN, (T_STEPS + BM - 1) / BM);   // (64, 16)
    gemm_nt_kernel<<<grid, 256>>>(x, weight, lif_ptr, T_STEPS, N_OUT, N_IN);

    // Scan: 128 CTAs x 1 warp
    lif_scan_kernel<<<128, 32>>>(lif_ptr, out,
                                 v_th, v_rest, v_reset, t_ref, tau);
}